// round 16
// baseline (speedup 1.0000x reference)
#include <cuda_runtime.h>
#include <math.h>

#define Bb 4
#define Nn 2048
#define Dd 1024
#define Hh 16
#define dhh 64
#define Ff 2048
#define PADn 8192
#define FBn 4097
#define NCn 32
#define PI_D 3.14159265358979323846

typedef unsigned long long ull;

__device__ float  g_qkvg[(size_t)Bb * Nn * 4 * Dd];
__device__ float  g_phiq[(size_t)Bb * Hh * Nn * dhh];
__device__ float  g_write[(size_t)Bb * Hh * Nn * 2 * dhh];
__device__ float  g_ctrl[Bb * Hh * NCn];
__device__ float  g_h1[Bb * Dd];
__device__ float2 g_mod[(size_t)Bb * Hh * FBn];
__device__ float  g_conv[(size_t)Bb * Hh * Ff * 2 * dhh];
__device__ float  g_att[(size_t)Bb * Nn * Dd];
__device__ float2 g_twid[PADn / 2];
__device__ double2 g_dtwid[PADn / 2];
__device__ float2 g_basefft[Hh * FBn];

__device__ __forceinline__ float2 cmulf(float2 a, float2 b) {
    return make_float2(a.x * b.x - a.y * b.y, a.x * b.y + a.y * b.x);
}
__device__ __forceinline__ float xla_sigmoid(float x) {
    return __fadd_rn(__fmul_rn(0.5f, tanhf(__fmul_rn(0.5f, x))), 0.5f);
}
__device__ __forceinline__ ull pack2(float lo, float hi) {
    ull r;
    asm("mov.b64 %0, {%1, %2};" : "=l"(r) : "r"(__float_as_uint(lo)), "r"(__float_as_uint(hi)));
    return r;
}
__device__ __forceinline__ ull dup2(float v) {
    ull r;
    asm("mov.b64 %0, {%1, %1};" : "=l"(r) : "r"(__float_as_uint(v)));
    return r;
}
__device__ __forceinline__ void fma2(ull& acc, ull a, ull b) {
    asm("fma.rn.f32x2 %0, %1, %2, %3;" : "=l"(acc) : "l"(a), "l"(b), "l"(acc));
}
__device__ __forceinline__ void unpack2(ull v, float& lo, float& hi) {
    unsigned l, h;
    asm("mov.b64 {%0, %1}, %2;" : "=r"(l), "=r"(h) : "l"(v));
    lo = __uint_as_float(l); hi = __uint_as_float(h);
}

// ---------------- twiddle tables ----------------
__global__ void twid_kernel() {
    int j = blockIdx.x * 256 + threadIdx.x;
    if (j < PADn / 2) {
        double th = -2.0 * PI_D * (double)j / (double)PADn;
        g_twid[j] = make_float2((float)cos(th), (float)sin(th));
        g_dtwid[j] = make_double2(cos(th), sin(th));
    }
}

// ---------------- faithful fp32 kern -> double FFT -> fp32 spectrum ----------------
__global__ void __launch_bounds__(512) kernfft_kernel(const float* __restrict__ wave_freq,
                                                      const float* __restrict__ wave_damp,
                                                      const float* __restrict__ wave_phase) {
    extern __shared__ double sd[];
    double* re = sd;
    double* im = sd + PADn;
    int h = blockIdx.x;
    int tid = threadIdx.x;
    float af = (float)exp((double)wave_damp[h]);
    float fr = wave_freq[h];
    float ph = wave_phase[h];

    for (int t = tid; t < PADn; t += 512) {
        float kv = 0.f;
        if (t < Ff) {
            float tf = (float)t / 2048.0f;
            float m1 = __fmul_rn(-af, tf);
            float e1 = (float)exp((double)m1);
            float arg = __fadd_rn(__fmul_rn(fr, tf), ph);
            float c1 = (float)cos((double)arg);
            kv = __fmul_rn(e1, c1);
        }
        int rv = __brev((unsigned)t) >> 19;
        re[rv] = (double)kv;
        im[rv] = 0.0;
    }
    __syncthreads();
#pragma unroll 1
    for (int s = 1; s <= 13; s++) {
        int half = 1 << (s - 1), shift = 13 - s;
        for (int idx = tid; idx < 4096; idx += 512) {
            int pos = idx & (half - 1);
            int base = ((idx >> (s - 1)) << s) + pos;
            double2 wv = g_dtwid[pos << shift];
            double ar = re[base], ai = im[base];
            double br = re[base + half], bi = im[base + half];
            double tr = br * wv.x - bi * wv.y;
            double ti = br * wv.y + bi * wv.x;
            re[base] = ar + tr; im[base] = ai + ti;
            re[base + half] = ar - tr; im[base + half] = ai - ti;
        }
        __syncthreads();
    }
    for (int k = tid; k < FBn; k += 512)
        g_basefft[h * FBn + k] = make_float2((float)re[k], (float)im[k]);
}

// ---------------- fp32 GEMM, 128x128 tile, 256 threads, 8x8 frags, FFMA2, ping-pong -
#define GS 132
__global__ void __launch_bounds__(256) gemm_nt(const float* __restrict__ A,
                                               const float* __restrict__ Bm,
                                               const float* __restrict__ bias,
                                               float* __restrict__ C,
                                               int M, int Nc, int K) {
    extern __shared__ float gsm[];
    float* As = gsm;
    float* Bs = gsm + 2 * 16 * GS;
    int tid = threadIdx.x;
    int m0 = blockIdx.y * 128, n0 = blockIdx.x * 128;
    int tm = tid >> 4, tn = tid & 15;
    int lr = tid >> 1, lk = (tid & 1) * 8;

    const float* Ap = A + (size_t)(m0 + lr) * K + lk;
    const float* Bp = Bm + (size_t)(n0 + lr) * K + lk;

    ull acc[8][4];
#pragma unroll
    for (int i = 0; i < 8; i++)
#pragma unroll
        for (int j = 0; j < 4; j++) acc[i][j] = 0ull;

    float4 ra0 = *(const float4*)Ap;
    float4 ra1 = *(const float4*)(Ap + 4);
    float4 rb0 = *(const float4*)Bp;
    float4 rb1 = *(const float4*)(Bp + 4);

    {
        float* a0 = As + lk * GS + lr;
        a0[0 * GS] = ra0.x; a0[1 * GS] = ra0.y; a0[2 * GS] = ra0.z; a0[3 * GS] = ra0.w;
        a0[4 * GS] = ra1.x; a0[5 * GS] = ra1.y; a0[6 * GS] = ra1.z; a0[7 * GS] = ra1.w;
        float* b0 = Bs + lk * GS + lr;
        b0[0 * GS] = rb0.x; b0[1 * GS] = rb0.y; b0[2 * GS] = rb0.z; b0[3 * GS] = rb0.w;
        b0[4 * GS] = rb1.x; b0[5 * GS] = rb1.y; b0[6 * GS] = rb1.z; b0[7 * GS] = rb1.w;
    }
    __syncthreads();
    int p = 0;
    for (int k0 = 0; k0 < K; k0 += 16) {
        bool more = (k0 + 16) < K;
        if (more) {
            Ap += 16; Bp += 16;
            ra0 = *(const float4*)Ap;
            ra1 = *(const float4*)(Ap + 4);
            rb0 = *(const float4*)Bp;
            rb1 = *(const float4*)(Bp + 4);
        }
        const float* Abuf = As + p * 16 * GS;
        const float* Bbuf = Bs + p * 16 * GS;
#pragma unroll
        for (int kk = 0; kk < 16; kk++) {
            float4 av0 = *(const float4*)(Abuf + kk * GS + tm * 8);
            float4 av1 = *(const float4*)(Abuf + kk * GS + tm * 8 + 4);
            float4 bv0 = *(const float4*)(Bbuf + kk * GS + tn * 4);
            float4 bv1 = *(const float4*)(Bbuf + kk * GS + 64 + tn * 4);
            ull bp0 = pack2(bv0.x, bv0.y), bp1 = pack2(bv0.z, bv0.w);
            ull bp2 = pack2(bv1.x, bv1.y), bp3 = pack2(bv1.z, bv1.w);
            float av[8] = {av0.x, av0.y, av0.z, av0.w, av1.x, av1.y, av1.z, av1.w};
#pragma unroll
            for (int i = 0; i < 8; i++) {
                ull ad = dup2(av[i]);
                fma2(acc[i][0], ad, bp0);
                fma2(acc[i][1], ad, bp1);
                fma2(acc[i][2], ad, bp2);
                fma2(acc[i][3], ad, bp3);
            }
        }
        if (more) {
            int q = p ^ 1;
            float* a0 = As + q * 16 * GS + lk * GS + lr;
            a0[0 * GS] = ra0.x; a0[1 * GS] = ra0.y; a0[2 * GS] = ra0.z; a0[3 * GS] = ra0.w;
            a0[4 * GS] = ra1.x; a0[5 * GS] = ra1.y; a0[6 * GS] = ra1.z; a0[7 * GS] = ra1.w;
            float* b0 = Bs + q * 16 * GS + lk * GS + lr;
            b0[0 * GS] = rb0.x; b0[1 * GS] = rb0.y; b0[2 * GS] = rb0.z; b0[3 * GS] = rb0.w;
            b0[4 * GS] = rb1.x; b0[5 * GS] = rb1.y; b0[6 * GS] = rb1.z; b0[7 * GS] = rb1.w;
            __syncthreads();
            p = q;
        }
    }
#pragma unroll
    for (int i = 0; i < 8; i++) {
        int row = m0 + tm * 8 + i;
        int c0 = n0 + tn * 4;
        int c1 = n0 + 64 + tn * 4;
        float o0, o1, o2, o3, o4, o5, o6, o7;
        unpack2(acc[i][0], o0, o1);
        unpack2(acc[i][1], o2, o3);
        unpack2(acc[i][2], o4, o5);
        unpack2(acc[i][3], o6, o7);
        float4 w0, w1;
        w0.x = o0 + bias[c0 + 0];
        w0.y = o1 + bias[c0 + 1];
        w0.z = o2 + bias[c0 + 2];
        w0.w = o3 + bias[c0 + 3];
        w1.x = o4 + bias[c1 + 0];
        w1.y = o5 + bias[c1 + 1];
        w1.z = o6 + bias[c1 + 2];
        w1.w = o7 + bias[c1 + 3];
        *(float4*)(C + (size_t)row * Nc + c0) = w0;
        *(float4*)(C + (size_t)row * Nc + c1) = w1;
    }
}
#define GEMM_SMEM (4 * 16 * GS * 4)

// ---------------- featmaps + write-gate: 2 rows/thread, weight-LDS halved ----------
// Per-output FMA chains identical (bias, then i=0..63 ascending) -> bit-identical.
#define FSPLIT 16
#define XR 68
__global__ void __launch_bounds__(256) featmap_kernel(const float* __restrict__ qfm_w,
                                                      const float* __restrict__ qfm_b,
                                                      const float* __restrict__ kfm_w,
                                                      const float* __restrict__ kfm_b,
                                                      const float* __restrict__ wg_w,
                                                      const float* __restrict__ wg_b) {
    extern __shared__ float fsm[];
    float* wt  = fsm;               // 2*4096
    float* xs  = fsm + 8192;        // 32*XR
    float* vs  = xs + 32 * XR;      // 32*XR
    float* t1s = vs + 32 * XR;      // 32*XR
    float* bsx = t1s + 32 * XR;     // 2*64
    float* wgw = bsx + 128;         // 64
    float* wgs = wgw + 64;          // 33 (last = wgb)

    int tid = threadIdx.x;
    int rp = tid >> 4;       // 0..15 -> rows rp, rp+16
    int jg = tid & 15;
    int bh = blockIdx.x / FSPLIT, sp = blockIdx.x % FSPLIT;
    int b = bh >> 4, h = bh & 15;
    int n0 = sp * (Nn / FSPLIT);
    size_t rowbase = (size_t)b * Nn * 4096 + h * 64;

    // ================= Q phase =================
    for (int e = tid; e < 8192; e += 256) {
        int l = e >> 12, idx = e & 4095;
        wt[l * 4096 + (idx & 63) * 64 + (idx >> 6)] = qfm_w[e];
    }
    if (tid < 128) bsx[(tid >> 6) * 64 + (tid & 63)] = qfm_b[tid];
    __syncthreads();
    for (int it = 0; it < Nn / FSPLIT; it += 32) {
        int na = n0 + it + rp;
        int nb = na + 16;
        *(float4*)&xs[rp * XR + jg * 4] =
            *(const float4*)&g_qkvg[rowbase + (size_t)na * 4096 + jg * 4];
        *(float4*)&xs[(rp + 16) * XR + jg * 4] =
            *(const float4*)&g_qkvg[rowbase + (size_t)nb * 4096 + jg * 4];
        __syncthreads();
        {
            float a0 = bsx[jg * 4 + 0], a1 = bsx[jg * 4 + 1];
            float a2 = bsx[jg * 4 + 2], a3 = bsx[jg * 4 + 3];
            float b0 = a0, b1 = a1, b2 = a2, b3 = a3;
#pragma unroll 4
            for (int i = 0; i < 64; i += 4) {
                float4 xa = *(const float4*)&xs[rp * XR + i];
                float4 xb = *(const float4*)&xs[(rp + 16) * XR + i];
                float4 w0 = *(const float4*)&wt[(i + 0) * 64 + jg * 4];
                a0 = __fmaf_rn(xa.x, w0.x, a0); a1 = __fmaf_rn(xa.x, w0.y, a1);
                a2 = __fmaf_rn(xa.x, w0.z, a2); a3 = __fmaf_rn(xa.x, w0.w, a3);
                b0 = __fmaf_rn(xb.x, w0.x, b0); b1 = __fmaf_rn(xb.x, w0.y, b1);
                b2 = __fmaf_rn(xb.x, w0.z, b2); b3 = __fmaf_rn(xb.x, w0.w, b3);
                float4 w1 = *(const float4*)&wt[(i + 1) * 64 + jg * 4];
                a0 = __fmaf_rn(xa.y, w1.x, a0); a1 = __fmaf_rn(xa.y, w1.y, a1);
                a2 = __fmaf_rn(xa.y, w1.z, a2); a3 = __fmaf_rn(xa.y, w1.w, a3);
                b0 = __fmaf_rn(xb.y, w1.x, b0); b1 = __fmaf_rn(xb.y, w1.y, b1);
                b2 = __fmaf_rn(xb.y, w1.z, b2); b3 = __fmaf_rn(xb.y, w1.w, b3);
                float4 w2 = *(const float4*)&wt[(i + 2) * 64 + jg * 4];
                a0 = __fmaf_rn(xa.z, w2.x, a0); a1 = __fmaf_rn(xa.z, w2.y, a1);
                a2 = __fmaf_rn(xa.z, w2.z, a2); a3 = __fmaf_rn(xa.z, w2.w, a3);
                b0 = __fmaf_rn(xb.z, w2.x, b0); b1 = __fmaf_rn(xb.z, w2.y, b1);
                b2 = __fmaf_rn(xb.z, w2.z, b2); b3 = __fmaf_rn(xb.z, w2.w, b3);
                float4 w3 = *(const float4*)&wt[(i + 3) * 64 + jg * 4];
                a0 = __fmaf_rn(xa.w, w3.x, a0); a1 = __fmaf_rn(xa.w, w3.y, a1);
                a2 = __fmaf_rn(xa.w, w3.z, a2); a3 = __fmaf_rn(xa.w, w3.w, a3);
                b0 = __fmaf_rn(xb.w, w3.x, b0); b1 = __fmaf_rn(xb.w, w3.y, b1);
                b2 = __fmaf_rn(xb.w, w3.z, b2); b3 = __fmaf_rn(xb.w, w3.w, b3);
            }
            float4 ta, tb;
            ta.x = fmaxf(a0, 0.f); ta.y = fmaxf(a1, 0.f);
            ta.z = fmaxf(a2, 0.f); ta.w = fmaxf(a3, 0.f);
            tb.x = fmaxf(b0, 0.f); tb.y = fmaxf(b1, 0.f);
            tb.z = fmaxf(b2, 0.f); tb.w = fmaxf(b3, 0.f);
            *(float4*)&t1s[rp * XR + jg * 4] = ta;
            *(float4*)&t1s[(rp + 16) * XR + jg * 4] = tb;
        }
        __syncthreads();
        {
            float a0 = bsx[64 + jg * 4 + 0], a1 = bsx[64 + jg * 4 + 1];
            float a2 = bsx[64 + jg * 4 + 2], a3 = bsx[64 + jg * 4 + 3];
            float b0 = a0, b1 = a1, b2 = a2, b3 = a3;
#pragma unroll 4
            for (int i = 0; i < 64; i += 4) {
                float4 xa = *(const float4*)&t1s[rp * XR + i];
                float4 xb = *(const float4*)&t1s[(rp + 16) * XR + i];
                float4 w0 = *(const float4*)&wt[4096 + (i + 0) * 64 + jg * 4];
                a0 = __fmaf_rn(xa.x, w0.x, a0); a1 = __fmaf_rn(xa.x, w0.y, a1);
                a2 = __fmaf_rn(xa.x, w0.z, a2); a3 = __fmaf_rn(xa.x, w0.w, a3);
                b0 = __fmaf_rn(xb.x, w0.x, b0); b1 = __fmaf_rn(xb.x, w0.y, b1);
                b2 = __fmaf_rn(xb.x, w0.z, b2); b3 = __fmaf_rn(xb.x, w0.w, b3);
                float4 w1 = *(const float4*)&wt[4096 + (i + 1) * 64 + jg * 4];
                a0 = __fmaf_rn(xa.y, w1.x, a0); a1 = __fmaf_rn(xa.y, w1.y, a1);
                a2 = __fmaf_rn(xa.y, w1.z, a2); a3 = __fmaf_rn(xa.y, w1.w, a3);
                b0 = __fmaf_rn(xb.y, w1.x, b0); b1 = __fmaf_rn(xb.y, w1.y, b1);
                b2 = __fmaf_rn(xb.y, w1.z, b2); b3 = __fmaf_rn(xb.y, w1.w, b3);
                float4 w2 = *(const float4*)&wt[4096 + (i + 2) * 64 + jg * 4];
                a0 = __fmaf_rn(xa.z, w2.x, a0); a1 = __fmaf_rn(xa.z, w2.y, a1);
                a2 = __fmaf_rn(xa.z, w2.z, a2); a3 = __fmaf_rn(xa.z, w2.w, a3);
                b0 = __fmaf_rn(xb.z, w2.x, b0); b1 = __fmaf_rn(xb.z, w2.y, b1);
                b2 = __fmaf_rn(xb.z, w2.z, b2); b3 = __fmaf_rn(xb.z, w2.w, b3);
                float4 w3 = *(const float4*)&wt[4096 + (i + 3) * 64 + jg * 4];
                a0 = __fmaf_rn(xa.w, w3.x, a0); a1 = __fmaf_rn(xa.w, w3.y, a1);
                a2 = __fmaf_rn(xa.w, w3.z, a2); a3 = __fmaf_rn(xa.w, w3.w, a3);
                b0 = __fmaf_rn(xb.w, w3.x, b0); b1 = __fmaf_rn(xb.w, w3.y, b1);
                b2 = __fmaf_rn(xb.w, w3.z, b2); b3 = __fmaf_rn(xb.w, w3.w, b3);
            }
            float4 pa, pb;
            pa.x = fmaxf(a0, 0.f) + 1e-6f; pa.y = fmaxf(a1, 0.f) + 1e-6f;
            pa.z = fmaxf(a2, 0.f) + 1e-6f; pa.w = fmaxf(a3, 0.f) + 1e-6f;
            pb.x = fmaxf(b0, 0.f) + 1e-6f; pb.y = fmaxf(b1, 0.f) + 1e-6f;
            pb.z = fmaxf(b2, 0.f) + 1e-6f; pb.w = fmaxf(b3, 0.f) + 1e-6f;
            *(float4*)&g_phiq[((size_t)bh * Nn + na) * 64 + jg * 4] = pa;
            *(float4*)&g_phiq[((size_t)bh * Nn + nb) * 64 + jg * 4] = pb;
        }
        __syncthreads();
    }
    __syncthreads();
    // ================= K phase =================
    for (int e = tid; e < 8192; e += 256) {
        int l = e >> 12, idx = e & 4095;
        wt[l * 4096 + (idx & 63) * 64 + (idx >> 6)] = kfm_w[e];
    }
    if (tid < 128) bsx[(tid >> 6) * 64 + (tid & 63)] = kfm_b[tid];
    if (tid < 64) wgw[tid] = wg_w[tid];
    if (tid == 0) wgs[32] = wg_b[0];
    __syncthreads();
    for (int it = 0; it < Nn / FSPLIT; it += 32) {
        int na = n0 + it + rp;
        int nb = na + 16;
        *(float4*)&xs[rp * XR + jg * 4] =
            *(const float4*)&g_qkvg[rowbase + (size_t)na * 4096 + 1024 + jg * 4];
        *(float4*)&xs[(rp + 16) * XR + jg * 4] =
            *(const float4*)&g_qkvg[rowbase + (size_t)nb * 4096 + 1024 + jg * 4];
        *(float4*)&vs[rp * XR + jg * 4] =
            *(const float4*)&g_qkvg[rowbase + (size_t)na * 4096 + 2048 + jg * 4];
        *(float4*)&vs[(rp + 16) * XR + jg * 4] =
            *(const float4*)&g_qkvg[rowbase + (size_t)nb * 4096 + 2048 + jg * 4];
        __syncthreads();
        {
            float a0 = bsx[jg * 4 + 0], a1 = bsx[jg * 4 + 1];
            float a2 = bsx[jg * 4 + 2], a3 = bsx[jg * 4 + 3];
            float b0 = a0, b1 = a1, b2 = a2, b3 = a3;
#pragma unroll 4
            for (int i = 0; i < 64; i += 4) {
                float4 xa = *(const float4*)&xs[rp * XR + i];
                float4 xb = *(const float4*)&xs[(rp + 16) * XR + i];
                float4 w0 = *(const float4*)&wt[(i + 0) * 64 + jg * 4];
                a0 = __fmaf_rn(xa.x, w0.x, a0); a1 = __fmaf_rn(xa.x, w0.y, a1);
                a2 = __fmaf_rn(xa.x, w0.z, a2); a3 = __fmaf_rn(xa.x, w0.w, a3);
                b0 = __fmaf_rn(xb.x, w0.x, b0); b1 = __fmaf_rn(xb.x, w0.y, b1);
                b2 = __fmaf_rn(xb.x, w0.z, b2); b3 = __fmaf_rn(xb.x, w0.w, b3);
                float4 w1 = *(const float4*)&wt[(i + 1) * 64 + jg * 4];
                a0 = __fmaf_rn(xa.y, w1.x, a0); a1 = __fmaf_rn(xa.y, w1.y, a1);
                a2 = __fmaf_rn(xa.y, w1.z, a2); a3 = __fmaf_rn(xa.y, w1.w, a3);
                b0 = __fmaf_rn(xb.y, w1.x, b0); b1 = __fmaf_rn(xb.y, w1.y, b1);
                b2 = __fmaf_rn(xb.y, w1.z, b2); b3 = __fmaf_rn(xb.y, w1.w, b3);
                float4 w2 = *(const float4*)&wt[(i + 2) * 64 + jg * 4];
                a0 = __fmaf_rn(xa.z, w2.x, a0); a1 = __fmaf_rn(xa.z, w2.y, a1);
                a2 = __fmaf_rn(xa.z, w2.z, a2); a3 = __fmaf_rn(xa.z, w2.w, a3);
                b0 = __fmaf_rn(xb.z, w2.x, b0); b1 = __fmaf_rn(xb.z, w2.y, b1);
                b2 = __fmaf_rn(xb.z, w2.z, b2); b3 = __fmaf_rn(xb.z, w2.w, b3);
                float4 w3 = *(const float4*)&wt[(i + 3) * 64 + jg * 4];
                a0 = __fmaf_rn(xa.w, w3.x, a0); a1 = __fmaf_rn(xa.w, w3.y, a1);
                a2 = __fmaf_rn(xa.w, w3.z, a2); a3 = __fmaf_rn(xa.w, w3.w, a3);
                b0 = __fmaf_rn(xb.w, w3.x, b0); b1 = __fmaf_rn(xb.w, w3.y, b1);
                b2 = __fmaf_rn(xb.w, w3.z, b2); b3 = __fmaf_rn(xb.w, w3.w, b3);
            }
            if (jg == 0) {
                float wa = wgs[32], wb = wgs[32];
#pragma unroll 8
                for (int i = 0; i < 64; i++) {
                    wa = __fmaf_rn(xs[rp * XR + i], wgw[i], wa);
                    wb = __fmaf_rn(xs[(rp + 16) * XR + i], wgw[i], wb);
                }
                wgs[rp] = xla_sigmoid(wa);
                wgs[rp + 16] = xla_sigmoid(wb);
            }
            float4 ta, tb;
            ta.x = fmaxf(a0, 0.f); ta.y = fmaxf(a1, 0.f);
            ta.z = fmaxf(a2, 0.f); ta.w = fmaxf(a3, 0.f);
            tb.x = fmaxf(b0, 0.f); tb.y = fmaxf(b1, 0.f);
            tb.z = fmaxf(b2, 0.f); tb.w = fmaxf(b3, 0.f);
            *(float4*)&t1s[rp * XR + jg * 4] = ta;
            *(float4*)&t1s[(rp + 16) * XR + jg * 4] = tb;
        }
        __syncthreads();
        {
            float a0 = bsx[64 + jg * 4 + 0], a1 = bsx[64 + jg * 4 + 1];
            float a2 = bsx[64 + jg * 4 + 2], a3 = bsx[64 + jg * 4 + 3];
            float b0 = a0, b1 = a1, b2 = a2, b3 = a3;
#pragma unroll 4
            for (int i = 0; i < 64; i += 4) {
                float4 xa = *(const float4*)&t1s[rp * XR + i];
                float4 xb = *(const float4*)&t1s[(rp + 16) * XR + i];
                float4 w0 = *(const float4*)&wt[4096 + (i + 0) * 64 + jg * 4];
                a0 = __fmaf_rn(xa.x, w0.x, a0); a1 = __fmaf_rn(xa.x, w0.y, a1);
                a2 = __fmaf_rn(xa.x, w0.z, a2); a3 = __fmaf_rn(xa.x, w0.w, a3);
                b0 = __fmaf_rn(xb.x, w0.x, b0); b1 = __fmaf_rn(xb.x, w0.y, b1);
                b2 = __fmaf_rn(xb.x, w0.z, b2); b3 = __fmaf_rn(xb.x, w0.w, b3);
                float4 w1 = *(const float4*)&wt[4096 + (i + 1) * 64 + jg * 4];
                a0 = __fmaf_rn(xa.y, w1.x, a0); a1 = __fmaf_rn(xa.y, w1.y, a1);
                a2 = __fmaf_rn(xa.y, w1.z, a2); a3 = __fmaf_rn(xa.y, w1.w, a3);
                b0 = __fmaf_rn(xb.y, w1.x, b0); b1 = __fmaf_rn(xb.y, w1.y, b1);
                b2 = __fmaf_rn(xb.y, w1.z, b2); b3 = __fmaf_rn(xb.y, w1.w, b3);
                float4 w2 = *(const float4*)&wt[4096 + (i + 2) * 64 + jg * 4];
                a0 = __fmaf_rn(xa.z, w2.x, a0); a1 = __fmaf_rn(xa.z, w2.y, a1);
                a2 = __fmaf_rn(xa.z, w2.z, a2); a3 = __fmaf_rn(xa.z, w2.w, a3);
                b0 = __fmaf_rn(xb.z, w2.x, b0); b1 = __fmaf_rn(xb.z, w2.y, b1);
                b2 = __fmaf_rn(xb.z, w2.z, b2); b3 = __fmaf_rn(xb.z, w2.w, b3);
                float4 w3 = *(const float4*)&wt[4096 + (i + 3) * 64 + jg * 4];
                a0 = __fmaf_rn(xa.w, w3.x, a0); a1 = __fmaf_rn(xa.w, w3.y, a1);
                a2 = __fmaf_rn(xa.w, w3.z, a2); a3 = __fmaf_rn(xa.w, w3.w, a3);
                b0 = __fmaf_rn(xb.w, w3.x, b0); b1 = __fmaf_rn(xb.w, w3.y, b1);
                b2 = __fmaf_rn(xb.w, w3.z, b2); b3 = __fmaf_rn(xb.w, w3.w, b3);
            }
            float wga = wgs[rp], wgb2 = wgs[rp + 16];
            float pa0 = fmaxf(a0, 0.f) + 1e-6f;
            float pa1 = fmaxf(a1, 0.f) + 1e-6f;
            float pa2 = fmaxf(a2, 0.f) + 1e-6f;
            float pa3 = fmaxf(a3, 0.f) + 1e-6f;
            float pb0 = fmaxf(b0, 0.f) + 1e-6f;
            float pb1 = fmaxf(b1, 0.f) + 1e-6f;
            float pb2 = fmaxf(b2, 0.f) + 1e-6f;
            float pb3 = fmaxf(b3, 0.f) + 1e-6f;
            float* wpa = &g_write[((size_t)bh * Nn + na) * 128];
            float* wpb = &g_write[((size_t)bh * Nn + nb) * 128];
            float4 o;
            o.x = wga * pa0 * vs[rp * XR + jg * 4 + 0];
            o.y = wga * pa1 * vs[rp * XR + jg * 4 + 1];
            o.z = wga * pa2 * vs[rp * XR + jg * 4 + 2];
            o.w = wga * pa3 * vs[rp * XR + jg * 4 + 3];
            *(float4*)(wpa + jg * 4) = o;
            o.x = wga * pa0; o.y = wga * pa1; o.z = wga * pa2; o.w = wga * pa3;
            *(float4*)(wpa + 64 + jg * 4) = o;
            o.x = wgb2 * pb0 * vs[(rp + 16) * XR + jg * 4 + 0];
            o.y = wgb2 * pb1 * vs[(rp + 16) * XR + jg * 4 + 1];
            o.z = wgb2 * pb2 * vs[(rp + 16) * XR + jg * 4 + 2];
            o.w = wgb2 * pb3 * vs[(rp + 16) * XR + jg * 4 + 3];
            *(float4*)(wpb + jg * 4) = o;
            o.x = wgb2 * pb0; o.y = wgb2 * pb1; o.z = wgb2 * pb2; o.w = wgb2 * pb3;
            *(float4*)(wpb + 64 + jg * 4) = o;
        }
        __syncthreads();
    }
}
#define FEAT_SMEM ((8192 + 3 * 32 * XR + 128 + 64 + 33) * 4)

// ---------------- spectral gate MLP (split) ----------------
__global__ void __launch_bounds__(256) sg1_kernel(const float* __restrict__ ln_g,
                                                  const float* __restrict__ ln_b,
                                                  const float* __restrict__ sg_w1,
                                                  const float* __restrict__ sg_b1) {
    __shared__ float q0[1024];
    __shared__ float mu[16], rv[16];
    int b = blockIdx.x >> 2, sl = blockIdx.x & 3;
    int tid = threadIdx.x;
    for (int i = tid; i < 1024; i += 256)
        q0[i] = g_qkvg[(size_t)b * Nn * 4096 + i];
    __syncthreads();
    if (tid < 16) {
        float s = 0.f;
        for (int j = 0; j < 64; j++) s += q0[tid * 64 + j];
        float m = s / 64.f;
        float s2 = 0.f;
        for (int j = 0; j < 64; j++) {
            float dv = __fsub_rn(q0[tid * 64 + j], m);
            s2 += dv * dv;
        }
        mu[tid] = m;
        rv[tid] = 1.f / sqrtf(s2 / 64.f + 1e-5f);
    }
    __syncthreads();
    for (int i = tid; i < 1024; i += 256) {
        int h = i >> 6, j = i & 63;
        q0[i] = (q0[i] - mu[h]) * rv[h] * ln_g[j] + ln_b[j];
    }
    __syncthreads();
    int o = sl * 256 + tid;
    float acc = sg_b1[o];
    const float* w = &sg_w1[(size_t)o * 1024];
    for (int i = 0; i < 1024; i++) acc += q0[i] * w[i];
    float cube = __fmul_rn(0.044715f, __fmul_rn(acc, __fmul_rn(acc, acc)));
    float t = tanhf(__fmul_rn(0.7978845608028654f, __fadd_rn(acc, cube)));
    g_h1[b * 1024 + o] = __fmul_rn(__fmul_rn(0.5f, acc), __fadd_rn(1.f, t));
}

__global__ void __launch_bounds__(256) sg2_kernel(const float* __restrict__ sg_w2,
                                                  const float* __restrict__ sg_b2) {
    __shared__ float h1[1024];
    int b = blockIdx.x >> 1, sl = blockIdx.x & 1;
    int tid = threadIdx.x;
    for (int i = tid; i < 1024; i += 256)
        h1[i] = g_h1[b * 1024 + i];
    __syncthreads();
    int o = sl * 256 + tid;
    float acc = sg_b2[o];
    const float* w = &sg_w2[(size_t)o * 1024];
    for (int i = 0; i < 1024; i++) acc += h1[i] * w[i];
    g_ctrl[b * 512 + o] = acc;
}

// ---------------- mod = fp32(basefft) * fp32(1+gate) / 8192 ----------------
__global__ void mod_kernel() {
    int bh = blockIdx.x, h = bh & 15;
    int k = blockIdx.y * 256 + threadIdx.x;
    if (k >= FBn) return;

    const float* cp = &g_ctrl[bh * NCn];
    float ip = (float)k * 31.0f / 4096.0f;
    int il = (int)ip; if (il > 30) il = 30; if (il < 0) il = 0;
    float iw = ip - (float)il;
    float gate = cp[il] * (1.f - iw) + cp[il + 1] * iw;
    float gf = 1.f + gate;

    float2 base = g_basefft[h * FBn + k];
    float mr = __fmul_rn(base.x, gf) * (1.0f / 8192.0f);
    float mi = __fmul_rn(base.y, gf) * (1.0f / 8192.0f);
    g_mod[(size_t)bh * FBn + k] = make_float2(mr, mi);
}

// ---------------- packed-pair 8192-pt FFT convolution, radix-2^3 fused passes -------
__global__ void __launch_bounds__(512) fft_conv_kernel() {
    extern __shared__ float2 sm[];
    float2* buf = sm;
    float2* tw = sm + PADn;
    int tid = threadIdx.x;
    int bh = blockIdx.x >> 6;
    int pr = blockIdx.x & 63;
    int c0 = pr * 2, c1 = c0 + 1;

    for (int j = tid; j < 4096; j += 512) tw[j] = g_twid[j];
    for (int t = tid; t < PADn; t += 512) {
        float re = 0.f, im = 0.f;
        if (t < 2047) {
            const float* wr = &g_write[((size_t)bh * Nn + t) * 128];
            re = wr[c0]; im = wr[c1];
            if (t == 2046) {
                const float* w2 = &g_write[((size_t)bh * Nn + 2047) * 128];
                re += w2[c0]; im += w2[c1];
            }
        }
        buf[__brev((unsigned)t) >> 19] = make_float2(re, im);
    }
    __syncthreads();
#pragma unroll 1
    for (int s = 1; s <= 10; s += 3) {
        int half = 1 << (s - 1);
        for (int q = tid; q < 1024; q += 512) {
            int pos = q & (half - 1);
            int base = ((q >> (s - 1)) << (s + 2)) + pos;
            float2 e[8];
#pragma unroll
            for (int j = 0; j < 8; j++) e[j] = buf[base + j * half];
            float2 w1 = tw[pos << (13 - s)];
#pragma unroll
            for (int j = 0; j < 8; j += 2) {
                float2 t1 = cmulf(e[j + 1], w1);
                float2 a = e[j];
                e[j]     = make_float2(a.x + t1.x, a.y + t1.y);
                e[j + 1] = make_float2(a.x - t1.x, a.y - t1.y);
            }
            float2 w2a = tw[pos << (12 - s)];
            float2 w2b = tw[(pos + half) << (12 - s)];
#pragma unroll
            for (int g = 0; g < 8; g += 4) {
#pragma unroll
                for (int j = 0; j < 2; j++) {
                    float2 wv = j ? w2b : w2a;
                    float2 t1 = cmulf(e[g + j + 2], wv);
                    float2 a = e[g + j];
                    e[g + j]     = make_float2(a.x + t1.x, a.y + t1.y);
                    e[g + j + 2] = make_float2(a.x - t1.x, a.y - t1.y);
                }
            }
#pragma unroll
            for (int j = 0; j < 4; j++) {
                float2 wv = tw[(pos + j * half) << (11 - s)];
                float2 t1 = cmulf(e[j + 4], wv);
                float2 a = e[j];
                e[j]     = make_float2(a.x + t1.x, a.y + t1.y);
                e[j + 4] = make_float2(a.x - t1.x, a.y - t1.y);
            }
#pragma unroll
            for (int j = 0; j < 8; j++) buf[base + j * half] = e[j];
        }
        __syncthreads();
    }
    for (int idx = tid; idx < 4096; idx += 512) {
        float2 wv = tw[idx];
        float2 av = buf[idx], bv = buf[idx + 4096];
        float2 bt = cmulf(bv, wv);
        buf[idx] = make_float2(av.x + bt.x, av.y + bt.y);
        buf[idx + 4096] = make_float2(av.x - bt.x, av.y - bt.y);
    }
    __syncthreads();
    const float2* modp = &g_mod[(size_t)bh * FBn];
    for (int k = tid; k < PADn; k += 512) {
        float2 m = (k <= 4096) ? modp[k] : modp[PADn - k];
        if (k > 4096) m.y = -m.y;
        buf[k] = cmulf(buf[k], m);
    }
    __syncthreads();
#pragma unroll 1
    for (int s = 13; s >= 4; s -= 3) {
        int Q = 1 << (s - 3);
        for (int q = tid; q < 1024; q += 512) {
            int pos = q & (Q - 1);
            int base = ((q >> (s - 3)) << s) + pos;
            float2 e[8];
#pragma unroll
            for (int j = 0; j < 8; j++) e[j] = buf[base + j * Q];
#pragma unroll
            for (int j = 0; j < 4; j++) {
                float2 wv = tw[(pos + j * Q) << (13 - s)]; wv.y = -wv.y;
                float2 a = e[j], bq = e[j + 4];
                e[j] = make_float2(a.x + bq.x, a.y + bq.y);
                e[j + 4] = cmulf(make_float2(a.x - bq.x, a.y - bq.y), wv);
            }
            float2 wma = tw[pos << (14 - s)]; wma.y = -wma.y;
            float2 wmb = tw[(pos + Q) << (14 - s)]; wmb.y = -wmb.y;
#pragma unroll
            for (int g = 0; g < 8; g += 4) {
#pragma unroll
                for (int j = 0; j < 2; j++) {
                    float2 wv = j ? wmb : wma;
                    float2 a = e[g + j], bq = e[g + j + 2];
                    e[g + j] = make_float2(a.x + bq.x, a.y + bq.y);
                    e[g + j + 2] = cmulf(make_float2(a.x - bq.x, a.y - bq.y), wv);
                }
            }
            float2 wl = tw[pos << (15 - s)]; wl.y = -wl.y;
#pragma unroll
            for (int j = 0; j < 8; j += 2) {
                float2 a = e[j], bq = e[j + 1];
                e[j] = make_float2(a.x + bq.x, a.y + bq.y);
                e[j + 1] = cmulf(make_float2(a.x - bq.x, a.y - bq.y), wl);
            }
#pragma unroll
            for (int j = 0; j < 8; j++) buf[base + j * Q] = e[j];
        }
        __syncthreads();
    }
    {
        float2 w0 = tw[0]; w0.y = -w0.y;
        for (int idx = tid; idx < 4096; idx += 512) {
            int base = idx * 2;
            float2 av = buf[base], bv = buf[base + 1];
            buf[base] = make_float2(av.x + bv.x, av.y + bv.y);
            float2 dv = make_float2(av.x - bv.x, av.y - bv.y);
            buf[base + 1] = cmulf(dv, w0);
        }
    }
    __syncthreads();
    for (int t = tid; t < Ff; t += 512) {
        float2 v = buf[__brev((unsigned)t) >> 19];
        float* cp = &g_conv[((size_t)bh * Ff + t) * 128];
        cp[c0] = v.x;
        cp[c1] = v.y;
    }
}

// ---------------- head coupling + gather + normalize + gate (256 threads) ----------
__global__ void __launch_bounds__(256) mix_kernel(const float* __restrict__ coupling) {
    __shared__ float convs[16 * 128];
    __shared__ float ys[16 * 128];
    __shared__ float coup[256];
    __shared__ float phiq[1024];
    __shared__ float den[16];
    int tid = threadIdx.x;
    int b = blockIdx.x >> 11, n = blockIdx.x & 2047;
    int fn = n < 2046 ? n : 2046;

    for (int i = tid; i < 2048; i += 256) {
        int g = i >> 7, c = i & 127;
        convs[i] = g_conv[(((size_t)(b * Hh + g)) * Ff + fn) * 128 + c];
    }
    if (tid < 256) coup[tid] = coupling[tid];
    for (int i = tid; i < 1024; i += 256) {
        int h = i >> 6, j = i & 63;
        phiq[i] = g_phiq[(((size_t)(b * Hh + h)) * Nn + n) * 64 + j];
    }
    __syncthreads();
    for (int i = tid; i < 2048; i += 256) {
        int h = i >> 7, c = i & 127;
        float acc = 0.f;
#pragma unroll
        for (int g = 0; g < 16; g++) acc += coup[h * 16 + g] * convs[g * 128 + c];
        ys[i] = acc;
    }
    __syncthreads();
    int warp = tid >> 5, lane = tid & 31;
    for (int h = warp; h < 16; h += 8) {
        float t1 = __fmul_rn(phiq[h * 64 + lane], ys[h * 128 + 64 + lane]);
        float t2 = __fmul_rn(phiq[h * 64 + 32 + lane], ys[h * 128 + 96 + lane]);
        float pv = __fadd_rn(t1, t2);
#pragma unroll
        for (int o = 16; o; o >>= 1)
            pv = __fadd_rn(pv, __shfl_down_sync(0xffffffffu, pv, o));
        pv = __shfl_sync(0xffffffffu, pv, 0);
        if (lane == 0) den[h] = __fadd_rn(fabsf(pv), 1e-4f);
    }
    __syncthreads();
    const float* grow = &g_qkvg[((size_t)b * Nn + n) * 4096 + 3072];
    float* arow = &g_att[((size_t)b * Nn + n) * 1024];
    for (int i = tid; i < 1024; i += 256) {
        int h = i >> 6;
        float sg = xla_sigmoid(grow[i]);
        arow[i] = phiq[i] * ys[h * 128 + (i & 63)] / den[h] * sg;
    }
}

// ---------------- launcher ----------------
extern "C" void kernel_launch(void* const* d_in, const int* in_sizes, int n_in,
                              void* d_out, int out_size) {
    const float* x       = (const float*)d_in[0];
    const float* w_qkvg  = (const float*)d_in[1];
    const float* b_qkvg  = (const float*)d_in[2];
    const float* w_out   = (const float*)d_in[3];
    const float* b_out   = (const float*)d_in[4];
    const float* qfm_w   = (const float*)d_in[5];
    const float* qfm_b   = (const float*)d_in[6];
    const float* kfm_w   = (const float*)d_in[7];
    const float* kfm_b   = (const float*)d_in[8];
    const float* wg_w    = (const float*)d_in[9];
    const float* wg_b    = (const float*)d_in[10];
    const float* ln_g    = (const float*)d_in[11];
    const float* ln_b    = (const float*)d_in[12];
    const float* sg_w1   = (const float*)d_in[13];
    const float* sg_b1   = (const float*)d_in[14];
    const float* sg_w2   = (const float*)d_in[15];
    const float* sg_b2   = (const float*)d_in[16];
    const float* wfreq   = (const float*)d_in[17];
    const float* wdamp   = (const float*)d_in[18];
    const float* wphase  = (const float*)d_in[19];
    const float* coupling= (const float*)d_in[20];
    (void)in_sizes; (void)n_in; (void)out_size;

    void* p;
    cudaGetSymbolAddress(&p, g_qkvg); float* qkvg = (float*)p;
    cudaGetSymbolAddress(&p, g_att);  float* att  = (float*)p;

    twid_kernel<<<16, 256>>>();
    cudaFuncSetAttribute(gemm_nt, cudaFuncAttributeMaxDynamicSharedMemorySize, GEMM_SMEM);
    gemm_nt<<<dim3(4096 / 128, 8192 / 128), 256, GEMM_SMEM>>>(x, w_qkvg, b_qkvg, qkvg, 8192, 4096, 1024);
    cudaFuncSetAttribute(kernfft_kernel, cudaFuncAttributeMaxDynamicSharedMemorySize, 131072);
    kernfft_kernel<<<Hh, 512, 131072>>>(wfreq, wdamp, wphase);
    cudaFuncSetAttribute(featmap_kernel, cudaFuncAttributeMaxDynamicSharedMemorySize, FEAT_SMEM);
    featmap_kernel<<<Bb * Hh * FSPLIT, 256, FEAT_SMEM>>>(qfm_w, qfm_b, kfm_w, kfm_b, wg_w, wg_b);
    sg1_kernel<<<Bb * 4, 256>>>(ln_g, ln_b, sg_w1, sg_b1);
    sg2_kernel<<<Bb * 2, 256>>>(sg_w2, sg_b2);
    mod_kernel<<<dim3(Bb * Hh, (FBn + 255) / 256), 256>>>();
    cudaFuncSetAttribute(fft_conv_kernel, cudaFuncAttributeMaxDynamicSharedMemorySize, 98304);
    fft_conv_kernel<<<Bb * Hh * 64, 512, 98304>>>();
    mix_kernel<<<Bb * Nn, 256>>>(coupling);
    gemm_nt<<<dim3(1024 / 128, 8192 / 128), 256, GEMM_SMEM>>>(att, w_out, b_out, (float*)d_out, 8192, 1024, 1024);
}

// round 17
// speedup vs baseline: 1.5816x; 1.5816x over previous
#include <cuda_runtime.h>
#include <math.h>

#define Bb 4
#define Nn 2048
#define Dd 1024
#define Hh 16
#define dhh 64
#define Ff 2048
#define PADn 8192
#define FBn 4097
#define NCn 32
#define PI_D 3.14159265358979323846

typedef unsigned long long ull;

__device__ float  g_qkvg[(size_t)Bb * Nn * 4 * Dd];
__device__ float  g_phiq[(size_t)Bb * Hh * Nn * dhh];
__device__ float  g_write[(size_t)Bb * Hh * Nn * 2 * dhh];
__device__ float  g_ctrl[Bb * Hh * NCn];
__device__ float  g_h1[Bb * Dd];
__device__ float2 g_mod[(size_t)Bb * Hh * FBn];
__device__ float  g_conv[(size_t)Bb * Hh * Ff * 2 * dhh];
__device__ float  g_att[(size_t)Bb * Nn * Dd];
__device__ float2 g_twid[PADn / 2];
__device__ double2 g_dtwid[PADn / 2];
__device__ float2 g_basefft[Hh * FBn];

__device__ __forceinline__ float2 cmulf(float2 a, float2 b) {
    return make_float2(a.x * b.x - a.y * b.y, a.x * b.y + a.y * b.x);
}
__device__ __forceinline__ float xla_sigmoid(float x) {
    return __fadd_rn(__fmul_rn(0.5f, tanhf(__fmul_rn(0.5f, x))), 0.5f);
}
__device__ __forceinline__ ull pack2(float lo, float hi) {
    ull r;
    asm("mov.b64 %0, {%1, %2};" : "=l"(r) : "r"(__float_as_uint(lo)), "r"(__float_as_uint(hi)));
    return r;
}
__device__ __forceinline__ ull dup2(float v) {
    ull r;
    asm("mov.b64 %0, {%1, %1};" : "=l"(r) : "r"(__float_as_uint(v)));
    return r;
}
__device__ __forceinline__ void fma2(ull& acc, ull a, ull b) {
    asm("fma.rn.f32x2 %0, %1, %2, %3;" : "=l"(acc) : "l"(a), "l"(b), "l"(acc));
}
__device__ __forceinline__ void unpack2(ull v, float& lo, float& hi) {
    unsigned l, h;
    asm("mov.b64 {%0, %1}, %2;" : "=r"(l), "=r"(h) : "l"(v));
    lo = __uint_as_float(l); hi = __uint_as_float(h);
}

// ---------------- twiddle tables ----------------
__global__ void twid_kernel() {
    int j = blockIdx.x * 256 + threadIdx.x;
    if (j < PADn / 2) {
        double th = -2.0 * PI_D * (double)j / (double)PADn;
        g_twid[j] = make_float2((float)cos(th), (float)sin(th));
        g_dtwid[j] = make_double2(cos(th), sin(th));
    }
}

// ---------------- faithful fp32 kern -> double FFT -> fp32 spectrum ----------------
__global__ void __launch_bounds__(512) kernfft_kernel(const float* __restrict__ wave_freq,
                                                      const float* __restrict__ wave_damp,
                                                      const float* __restrict__ wave_phase) {
    extern __shared__ double sd[];
    double* re = sd;
    double* im = sd + PADn;
    int h = blockIdx.x;
    int tid = threadIdx.x;
    float af = (float)exp((double)wave_damp[h]);
    float fr = wave_freq[h];
    float ph = wave_phase[h];

    for (int t = tid; t < PADn; t += 512) {
        float kv = 0.f;
        if (t < Ff) {
            float tf = (float)t / 2048.0f;
            float m1 = __fmul_rn(-af, tf);
            float e1 = (float)exp((double)m1);
            float arg = __fadd_rn(__fmul_rn(fr, tf), ph);
            float c1 = (float)cos((double)arg);
            kv = __fmul_rn(e1, c1);
        }
        int rv = __brev((unsigned)t) >> 19;
        re[rv] = (double)kv;
        im[rv] = 0.0;
    }
    __syncthreads();
#pragma unroll 1
    for (int s = 1; s <= 13; s++) {
        int half = 1 << (s - 1), shift = 13 - s;
        for (int idx = tid; idx < 4096; idx += 512) {
            int pos = idx & (half - 1);
            int base = ((idx >> (s - 1)) << s) + pos;
            double2 wv = g_dtwid[pos << shift];
            double ar = re[base], ai = im[base];
            double br = re[base + half], bi = im[base + half];
            double tr = br * wv.x - bi * wv.y;
            double ti = br * wv.y + bi * wv.x;
            re[base] = ar + tr; im[base] = ai + ti;
            re[base + half] = ar - tr; im[base + half] = ai - ti;
        }
        __syncthreads();
    }
    for (int k = tid; k < FBn; k += 512)
        g_basefft[h * FBn + k] = make_float2((float)re[k], (float)im[k]);
}

// ---------------- fp32 GEMM, 128x128 tile, 256 threads, 8x8 frags, FFMA2, ping-pong -
#define GS 132
__global__ void __launch_bounds__(256) gemm_nt(const float* __restrict__ A,
                                               const float* __restrict__ Bm,
                                               const float* __restrict__ bias,
                                               float* __restrict__ C,
                                               int M, int Nc, int K) {
    extern __shared__ float gsm[];
    float* As = gsm;
    float* Bs = gsm + 2 * 16 * GS;
    int tid = threadIdx.x;
    int m0 = blockIdx.y * 128, n0 = blockIdx.x * 128;
    int tm = tid >> 4, tn = tid & 15;
    int lr = tid >> 1, lk = (tid & 1) * 8;

    const float* Ap = A + (size_t)(m0 + lr) * K + lk;
    const float* Bp = Bm + (size_t)(n0 + lr) * K + lk;

    ull acc[8][4];
#pragma unroll
    for (int i = 0; i < 8; i++)
#pragma unroll
        for (int j = 0; j < 4; j++) acc[i][j] = 0ull;

    float4 ra0 = *(const float4*)Ap;
    float4 ra1 = *(const float4*)(Ap + 4);
    float4 rb0 = *(const float4*)Bp;
    float4 rb1 = *(const float4*)(Bp + 4);

    {
        float* a0 = As + lk * GS + lr;
        a0[0 * GS] = ra0.x; a0[1 * GS] = ra0.y; a0[2 * GS] = ra0.z; a0[3 * GS] = ra0.w;
        a0[4 * GS] = ra1.x; a0[5 * GS] = ra1.y; a0[6 * GS] = ra1.z; a0[7 * GS] = ra1.w;
        float* b0 = Bs + lk * GS + lr;
        b0[0 * GS] = rb0.x; b0[1 * GS] = rb0.y; b0[2 * GS] = rb0.z; b0[3 * GS] = rb0.w;
        b0[4 * GS] = rb1.x; b0[5 * GS] = rb1.y; b0[6 * GS] = rb1.z; b0[7 * GS] = rb1.w;
    }
    __syncthreads();
    int p = 0;
    for (int k0 = 0; k0 < K; k0 += 16) {
        bool more = (k0 + 16) < K;
        if (more) {
            Ap += 16; Bp += 16;
            ra0 = *(const float4*)Ap;
            ra1 = *(const float4*)(Ap + 4);
            rb0 = *(const float4*)Bp;
            rb1 = *(const float4*)(Bp + 4);
        }
        const float* Abuf = As + p * 16 * GS;
        const float* Bbuf = Bs + p * 16 * GS;
#pragma unroll
        for (int kk = 0; kk < 16; kk++) {
            float4 av0 = *(const float4*)(Abuf + kk * GS + tm * 8);
            float4 av1 = *(const float4*)(Abuf + kk * GS + tm * 8 + 4);
            float4 bv0 = *(const float4*)(Bbuf + kk * GS + tn * 4);
            float4 bv1 = *(const float4*)(Bbuf + kk * GS + 64 + tn * 4);
            ull bp0 = pack2(bv0.x, bv0.y), bp1 = pack2(bv0.z, bv0.w);
            ull bp2 = pack2(bv1.x, bv1.y), bp3 = pack2(bv1.z, bv1.w);
            float av[8] = {av0.x, av0.y, av0.z, av0.w, av1.x, av1.y, av1.z, av1.w};
#pragma unroll
            for (int i = 0; i < 8; i++) {
                ull ad = dup2(av[i]);
                fma2(acc[i][0], ad, bp0);
                fma2(acc[i][1], ad, bp1);
                fma2(acc[i][2], ad, bp2);
                fma2(acc[i][3], ad, bp3);
            }
        }
        if (more) {
            int q = p ^ 1;
            float* a0 = As + q * 16 * GS + lk * GS + lr;
            a0[0 * GS] = ra0.x; a0[1 * GS] = ra0.y; a0[2 * GS] = ra0.z; a0[3 * GS] = ra0.w;
            a0[4 * GS] = ra1.x; a0[5 * GS] = ra1.y; a0[6 * GS] = ra1.z; a0[7 * GS] = ra1.w;
            float* b0 = Bs + q * 16 * GS + lk * GS + lr;
            b0[0 * GS] = rb0.x; b0[1 * GS] = rb0.y; b0[2 * GS] = rb0.z; b0[3 * GS] = rb0.w;
            b0[4 * GS] = rb1.x; b0[5 * GS] = rb1.y; b0[6 * GS] = rb1.z; b0[7 * GS] = rb1.w;
            __syncthreads();
            p = q;
        }
    }
#pragma unroll
    for (int i = 0; i < 8; i++) {
        int row = m0 + tm * 8 + i;
        int c0 = n0 + tn * 4;
        int c1 = n0 + 64 + tn * 4;
        float o0, o1, o2, o3, o4, o5, o6, o7;
        unpack2(acc[i][0], o0, o1);
        unpack2(acc[i][1], o2, o3);
        unpack2(acc[i][2], o4, o5);
        unpack2(acc[i][3], o6, o7);
        float4 w0, w1;
        w0.x = o0 + bias[c0 + 0];
        w0.y = o1 + bias[c0 + 1];
        w0.z = o2 + bias[c0 + 2];
        w0.w = o3 + bias[c0 + 3];
        w1.x = o4 + bias[c1 + 0];
        w1.y = o5 + bias[c1 + 1];
        w1.z = o6 + bias[c1 + 2];
        w1.w = o7 + bias[c1 + 3];
        *(float4*)(C + (size_t)row * Nc + c0) = w0;
        *(float4*)(C + (size_t)row * Nc + c1) = w1;
    }
}
#define GEMM_SMEM (4 * 16 * GS * 4)

// ---------------- featmaps + write-gate (R14 version: static smem, 1 row/thread) ----
#define FSPLIT 16
__global__ void __launch_bounds__(256) featmap_kernel(const float* __restrict__ qfm_w,
                                                      const float* __restrict__ qfm_b,
                                                      const float* __restrict__ kfm_w,
                                                      const float* __restrict__ kfm_b,
                                                      const float* __restrict__ wg_w,
                                                      const float* __restrict__ wg_b) {
    __shared__ float wt[2][4096];
    __shared__ float bs[2][64];
    __shared__ __align__(16) float xs[16][68];
    __shared__ __align__(16) float vs[16][68];
    __shared__ __align__(16) float t1s[16][68];
    __shared__ float wgw[64];
    __shared__ float wgs[16];
    __shared__ float wgb;

    int tid = threadIdx.x;
    int r = tid >> 4;
    int jg = tid & 15;
    int bh = blockIdx.x / FSPLIT, sp = blockIdx.x % FSPLIT;
    int b = bh >> 4, h = bh & 15;
    int n0 = sp * (Nn / FSPLIT);
    size_t rowbase = (size_t)b * Nn * 4096 + h * 64;

    for (int e = tid; e < 8192; e += 256) {
        int l = e >> 12, idx = e & 4095;
        wt[l][(idx & 63) * 64 + (idx >> 6)] = qfm_w[e];
    }
    if (tid < 128) bs[tid >> 6][tid & 63] = qfm_b[tid];
    __syncthreads();
    for (int it = 0; it < Nn / FSPLIT; it += 16) {
        int n = n0 + it + r;
        *(float4*)&xs[r][jg * 4] =
            *(const float4*)&g_qkvg[rowbase + (size_t)n * 4096 + jg * 4];
        __syncthreads();
        float a0 = bs[0][jg * 4 + 0], a1 = bs[0][jg * 4 + 1];
        float a2 = bs[0][jg * 4 + 2], a3 = bs[0][jg * 4 + 3];
#pragma unroll 4
        for (int i = 0; i < 64; i += 4) {
            float4 x4 = *(const float4*)&xs[r][i];
            float4 w0 = *(const float4*)&wt[0][(i + 0) * 64 + jg * 4];
            a0 = __fmaf_rn(x4.x, w0.x, a0); a1 = __fmaf_rn(x4.x, w0.y, a1);
            a2 = __fmaf_rn(x4.x, w0.z, a2); a3 = __fmaf_rn(x4.x, w0.w, a3);
            float4 w1 = *(const float4*)&wt[0][(i + 1) * 64 + jg * 4];
            a0 = __fmaf_rn(x4.y, w1.x, a0); a1 = __fmaf_rn(x4.y, w1.y, a1);
            a2 = __fmaf_rn(x4.y, w1.z, a2); a3 = __fmaf_rn(x4.y, w1.w, a3);
            float4 w2 = *(const float4*)&wt[0][(i + 2) * 64 + jg * 4];
            a0 = __fmaf_rn(x4.z, w2.x, a0); a1 = __fmaf_rn(x4.z, w2.y, a1);
            a2 = __fmaf_rn(x4.z, w2.z, a2); a3 = __fmaf_rn(x4.z, w2.w, a3);
            float4 w3 = *(const float4*)&wt[0][(i + 3) * 64 + jg * 4];
            a0 = __fmaf_rn(x4.w, w3.x, a0); a1 = __fmaf_rn(x4.w, w3.y, a1);
            a2 = __fmaf_rn(x4.w, w3.z, a2); a3 = __fmaf_rn(x4.w, w3.w, a3);
        }
        float4 t1v;
        t1v.x = fmaxf(a0, 0.f); t1v.y = fmaxf(a1, 0.f);
        t1v.z = fmaxf(a2, 0.f); t1v.w = fmaxf(a3, 0.f);
        *(float4*)&t1s[r][jg * 4] = t1v;
        __syncthreads();
        float c0 = bs[1][jg * 4 + 0], c1 = bs[1][jg * 4 + 1];
        float c2 = bs[1][jg * 4 + 2], c3 = bs[1][jg * 4 + 3];
#pragma unroll 4
        for (int i = 0; i < 64; i += 4) {
            float4 x4 = *(const float4*)&t1s[r][i];
            float4 w0 = *(const float4*)&wt[1][(i + 0) * 64 + jg * 4];
            c0 = __fmaf_rn(x4.x, w0.x, c0); c1 = __fmaf_rn(x4.x, w0.y, c1);
            c2 = __fmaf_rn(x4.x, w0.z, c2); c3 = __fmaf_rn(x4.x, w0.w, c3);
            float4 w1 = *(const float4*)&wt[1][(i + 1) * 64 + jg * 4];
            c0 = __fmaf_rn(x4.y, w1.x, c0); c1 = __fmaf_rn(x4.y, w1.y, c1);
            c2 = __fmaf_rn(x4.y, w1.z, c2); c3 = __fmaf_rn(x4.y, w1.w, c3);
            float4 w2 = *(const float4*)&wt[1][(i + 2) * 64 + jg * 4];
            c0 = __fmaf_rn(x4.z, w2.x, c0); c1 = __fmaf_rn(x4.z, w2.y, c1);
            c2 = __fmaf_rn(x4.z, w2.z, c2); c3 = __fmaf_rn(x4.z, w2.w, c3);
            float4 w3 = *(const float4*)&wt[1][(i + 3) * 64 + jg * 4];
            c0 = __fmaf_rn(x4.w, w3.x, c0); c1 = __fmaf_rn(x4.w, w3.y, c1);
            c2 = __fmaf_rn(x4.w, w3.z, c2); c3 = __fmaf_rn(x4.w, w3.w, c3);
        }
        float4 phi;
        phi.x = fmaxf(c0, 0.f) + 1e-6f;
        phi.y = fmaxf(c1, 0.f) + 1e-6f;
        phi.z = fmaxf(c2, 0.f) + 1e-6f;
        phi.w = fmaxf(c3, 0.f) + 1e-6f;
        *(float4*)&g_phiq[((size_t)bh * Nn + n) * 64 + jg * 4] = phi;
        __syncthreads();
    }
    __syncthreads();
    for (int e = tid; e < 8192; e += 256) {
        int l = e >> 12, idx = e & 4095;
        wt[l][(idx & 63) * 64 + (idx >> 6)] = kfm_w[e];
    }
    if (tid < 128) bs[tid >> 6][tid & 63] = kfm_b[tid];
    if (tid < 64) wgw[tid] = wg_w[tid];
    if (tid == 0) wgb = wg_b[0];
    __syncthreads();
    for (int it = 0; it < Nn / FSPLIT; it += 16) {
        int n = n0 + it + r;
        *(float4*)&xs[r][jg * 4] =
            *(const float4*)&g_qkvg[rowbase + (size_t)n * 4096 + 1024 + jg * 4];
        *(float4*)&vs[r][jg * 4] =
            *(const float4*)&g_qkvg[rowbase + (size_t)n * 4096 + 2048 + jg * 4];
        __syncthreads();
        float a0 = bs[0][jg * 4 + 0], a1 = bs[0][jg * 4 + 1];
        float a2 = bs[0][jg * 4 + 2], a3 = bs[0][jg * 4 + 3];
#pragma unroll 4
        for (int i = 0; i < 64; i += 4) {
            float4 x4 = *(const float4*)&xs[r][i];
            float4 w0 = *(const float4*)&wt[0][(i + 0) * 64 + jg * 4];
            a0 = __fmaf_rn(x4.x, w0.x, a0); a1 = __fmaf_rn(x4.x, w0.y, a1);
            a2 = __fmaf_rn(x4.x, w0.z, a2); a3 = __fmaf_rn(x4.x, w0.w, a3);
            float4 w1 = *(const float4*)&wt[0][(i + 1) * 64 + jg * 4];
            a0 = __fmaf_rn(x4.y, w1.x, a0); a1 = __fmaf_rn(x4.y, w1.y, a1);
            a2 = __fmaf_rn(x4.y, w1.z, a2); a3 = __fmaf_rn(x4.y, w1.w, a3);
            float4 w2 = *(const float4*)&wt[0][(i + 2) * 64 + jg * 4];
            a0 = __fmaf_rn(x4.z, w2.x, a0); a1 = __fmaf_rn(x4.z, w2.y, a1);
            a2 = __fmaf_rn(x4.z, w2.z, a2); a3 = __fmaf_rn(x4.z, w2.w, a3);
            float4 w3 = *(const float4*)&wt[0][(i + 3) * 64 + jg * 4];
            a0 = __fmaf_rn(x4.w, w3.x, a0); a1 = __fmaf_rn(x4.w, w3.y, a1);
            a2 = __fmaf_rn(x4.w, w3.z, a2); a3 = __fmaf_rn(x4.w, w3.w, a3);
        }
        if (jg == 0) {
            float wgacc = wgb;
#pragma unroll 8
            for (int i = 0; i < 64; i++)
                wgacc = __fmaf_rn(xs[r][i], wgw[i], wgacc);
            wgs[r] = xla_sigmoid(wgacc);
        }
        float4 t1v;
        t1v.x = fmaxf(a0, 0.f); t1v.y = fmaxf(a1, 0.f);
        t1v.z = fmaxf(a2, 0.f); t1v.w = fmaxf(a3, 0.f);
        *(float4*)&t1s[r][jg * 4] = t1v;
        __syncthreads();
        float c0 = bs[1][jg * 4 + 0], c1 = bs[1][jg * 4 + 1];
        float c2 = bs[1][jg * 4 + 2], c3 = bs[1][jg * 4 + 3];
#pragma unroll 4
        for (int i = 0; i < 64; i += 4) {
            float4 x4 = *(const float4*)&t1s[r][i];
            float4 w0 = *(const float4*)&wt[1][(i + 0) * 64 + jg * 4];
            c0 = __fmaf_rn(x4.x, w0.x, c0); c1 = __fmaf_rn(x4.x, w0.y, c1);
            c2 = __fmaf_rn(x4.x, w0.z, c2); c3 = __fmaf_rn(x4.x, w0.w, c3);
            float4 w1 = *(const float4*)&wt[1][(i + 1) * 64 + jg * 4];
            c0 = __fmaf_rn(x4.y, w1.x, c0); c1 = __fmaf_rn(x4.y, w1.y, c1);
            c2 = __fmaf_rn(x4.y, w1.z, c2); c3 = __fmaf_rn(x4.y, w1.w, c3);
            float4 w2 = *(const float4*)&wt[1][(i + 2) * 64 + jg * 4];
            c0 = __fmaf_rn(x4.z, w2.x, c0); c1 = __fmaf_rn(x4.z, w2.y, c1);
            c2 = __fmaf_rn(x4.z, w2.z, c2); c3 = __fmaf_rn(x4.z, w2.w, c3);
            float4 w3 = *(const float4*)&wt[1][(i + 3) * 64 + jg * 4];
            c0 = __fmaf_rn(x4.w, w3.x, c0); c1 = __fmaf_rn(x4.w, w3.y, c1);
            c2 = __fmaf_rn(x4.w, w3.z, c2); c3 = __fmaf_rn(x4.w, w3.w, c3);
        }
        float wgv = wgs[r];
        float p0 = fmaxf(c0, 0.f) + 1e-6f;
        float p1 = fmaxf(c1, 0.f) + 1e-6f;
        float p2 = fmaxf(c2, 0.f) + 1e-6f;
        float p3 = fmaxf(c3, 0.f) + 1e-6f;
        float* wp = &g_write[((size_t)bh * Nn + n) * 128];
        float4 wnum;
        wnum.x = wgv * p0 * vs[r][jg * 4 + 0];
        wnum.y = wgv * p1 * vs[r][jg * 4 + 1];
        wnum.z = wgv * p2 * vs[r][jg * 4 + 2];
        wnum.w = wgv * p3 * vs[r][jg * 4 + 3];
        *(float4*)(wp + jg * 4) = wnum;
        float4 wden;
        wden.x = wgv * p0; wden.y = wgv * p1; wden.z = wgv * p2; wden.w = wgv * p3;
        *(float4*)(wp + 64 + jg * 4) = wden;
        __syncthreads();
    }
}

// ---------------- spectral gate MLP (split) ----------------
__global__ void __launch_bounds__(256) sg1_kernel(const float* __restrict__ ln_g,
                                                  const float* __restrict__ ln_b,
                                                  const float* __restrict__ sg_w1,
                                                  const float* __restrict__ sg_b1) {
    __shared__ float q0[1024];
    __shared__ float mu[16], rv[16];
    int b = blockIdx.x >> 2, sl = blockIdx.x & 3;
    int tid = threadIdx.x;
    for (int i = tid; i < 1024; i += 256)
        q0[i] = g_qkvg[(size_t)b * Nn * 4096 + i];
    __syncthreads();
    if (tid < 16) {
        float s = 0.f;
        for (int j = 0; j < 64; j++) s += q0[tid * 64 + j];
        float m = s / 64.f;
        float s2 = 0.f;
        for (int j = 0; j < 64; j++) {
            float dv = __fsub_rn(q0[tid * 64 + j], m);
            s2 += dv * dv;
        }
        mu[tid] = m;
        rv[tid] = 1.f / sqrtf(s2 / 64.f + 1e-5f);
    }
    __syncthreads();
    for (int i = tid; i < 1024; i += 256) {
        int h = i >> 6, j = i & 63;
        q0[i] = (q0[i] - mu[h]) * rv[h] * ln_g[j] + ln_b[j];
    }
    __syncthreads();
    int o = sl * 256 + tid;
    float acc = sg_b1[o];
    const float* w = &sg_w1[(size_t)o * 1024];
    for (int i = 0; i < 1024; i++) acc += q0[i] * w[i];
    float cube = __fmul_rn(0.044715f, __fmul_rn(acc, __fmul_rn(acc, acc)));
    float t = tanhf(__fmul_rn(0.7978845608028654f, __fadd_rn(acc, cube)));
    g_h1[b * 1024 + o] = __fmul_rn(__fmul_rn(0.5f, acc), __fadd_rn(1.f, t));
}

__global__ void __launch_bounds__(256) sg2_kernel(const float* __restrict__ sg_w2,
                                                  const float* __restrict__ sg_b2) {
    __shared__ float h1[1024];
    int b = blockIdx.x >> 1, sl = blockIdx.x & 1;
    int tid = threadIdx.x;
    for (int i = tid; i < 1024; i += 256)
        h1[i] = g_h1[b * 1024 + i];
    __syncthreads();
    int o = sl * 256 + tid;
    float acc = sg_b2[o];
    const float* w = &sg_w2[(size_t)o * 1024];
    for (int i = 0; i < 1024; i++) acc += h1[i] * w[i];
    g_ctrl[b * 512 + o] = acc;
}

// ---------------- mod = fp32(basefft) * fp32(1+gate) / 8192 ----------------
__global__ void mod_kernel() {
    int bh = blockIdx.x, h = bh & 15;
    int k = blockIdx.y * 256 + threadIdx.x;
    if (k >= FBn) return;

    const float* cp = &g_ctrl[bh * NCn];
    float ip = (float)k * 31.0f / 4096.0f;
    int il = (int)ip; if (il > 30) il = 30; if (il < 0) il = 0;
    float iw = ip - (float)il;
    float gate = cp[il] * (1.f - iw) + cp[il + 1] * iw;
    float gf = 1.f + gate;

    float2 base = g_basefft[h * FBn + k];
    float mr = __fmul_rn(base.x, gf) * (1.0f / 8192.0f);
    float mi = __fmul_rn(base.y, gf) * (1.0f / 8192.0f);
    g_mod[(size_t)bh * FBn + k] = make_float2(mr, mi);
}

// ---------------- packed-pair 8192-pt FFT convolution, radix-2^3 fused passes -------
__global__ void __launch_bounds__(512) fft_conv_kernel() {
    extern __shared__ float2 sm[];
    float2* buf = sm;
    float2* tw = sm + PADn;
    int tid = threadIdx.x;
    int bh = blockIdx.x >> 6;
    int pr = blockIdx.x & 63;
    int c0 = pr * 2, c1 = c0 + 1;

    for (int j = tid; j < 4096; j += 512) tw[j] = g_twid[j];
    for (int t = tid; t < PADn; t += 512) {
        float re = 0.f, im = 0.f;
        if (t < 2047) {
            const float* wr = &g_write[((size_t)bh * Nn + t) * 128];
            re = wr[c0]; im = wr[c1];
            if (t == 2046) {
                const float* w2 = &g_write[((size_t)bh * Nn + 2047) * 128];
                re += w2[c0]; im += w2[c1];
            }
        }
        buf[__brev((unsigned)t) >> 19] = make_float2(re, im);
    }
    __syncthreads();
#pragma unroll 1
    for (int s = 1; s <= 10; s += 3) {
        int half = 1 << (s - 1);
        for (int q = tid; q < 1024; q += 512) {
            int pos = q & (half - 1);
            int base = ((q >> (s - 1)) << (s + 2)) + pos;
            float2 e[8];
#pragma unroll
            for (int j = 0; j < 8; j++) e[j] = buf[base + j * half];
            float2 w1 = tw[pos << (13 - s)];
#pragma unroll
            for (int j = 0; j < 8; j += 2) {
                float2 t1 = cmulf(e[j + 1], w1);
                float2 a = e[j];
                e[j]     = make_float2(a.x + t1.x, a.y + t1.y);
                e[j + 1] = make_float2(a.x - t1.x, a.y - t1.y);
            }
            float2 w2a = tw[pos << (12 - s)];
            float2 w2b = tw[(pos + half) << (12 - s)];
#pragma unroll
            for (int g = 0; g < 8; g += 4) {
#pragma unroll
                for (int j = 0; j < 2; j++) {
                    float2 wv = j ? w2b : w2a;
                    float2 t1 = cmulf(e[g + j + 2], wv);
                    float2 a = e[g + j];
                    e[g + j]     = make_float2(a.x + t1.x, a.y + t1.y);
                    e[g + j + 2] = make_float2(a.x - t1.x, a.y - t1.y);
                }
            }
#pragma unroll
            for (int j = 0; j < 4; j++) {
                float2 wv = tw[(pos + j * half) << (11 - s)];
                float2 t1 = cmulf(e[j + 4], wv);
                float2 a = e[j];
                e[j]     = make_float2(a.x + t1.x, a.y + t1.y);
                e[j + 4] = make_float2(a.x - t1.x, a.y - t1.y);
            }
#pragma unroll
            for (int j = 0; j < 8; j++) buf[base + j * half] = e[j];
        }
        __syncthreads();
    }
    for (int idx = tid; idx < 4096; idx += 512) {
        float2 wv = tw[idx];
        float2 av = buf[idx], bv = buf[idx + 4096];
        float2 bt = cmulf(bv, wv);
        buf[idx] = make_float2(av.x + bt.x, av.y + bt.y);
        buf[idx + 4096] = make_float2(av.x - bt.x, av.y - bt.y);
    }
    __syncthreads();
    const float2* modp = &g_mod[(size_t)bh * FBn];
    for (int k = tid; k < PADn; k += 512) {
        float2 m = (k <= 4096) ? modp[k] : modp[PADn - k];
        if (k > 4096) m.y = -m.y;
        buf[k] = cmulf(buf[k], m);
    }
    __syncthreads();
#pragma unroll 1
    for (int s = 13; s >= 4; s -= 3) {
        int Q = 1 << (s - 3);
        for (int q = tid; q < 1024; q += 512) {
            int pos = q & (Q - 1);
            int base = ((q >> (s - 3)) << s) + pos;
            float2 e[8];
#pragma unroll
            for (int j = 0; j < 8; j++) e[j] = buf[base + j * Q];
#pragma unroll
            for (int j = 0; j < 4; j++) {
                float2 wv = tw[(pos + j * Q) << (13 - s)]; wv.y = -wv.y;
                float2 a = e[j], bq = e[j + 4];
                e[j] = make_float2(a.x + bq.x, a.y + bq.y);
                e[j + 4] = cmulf(make_float2(a.x - bq.x, a.y - bq.y), wv);
            }
            float2 wma = tw[pos << (14 - s)]; wma.y = -wma.y;
            float2 wmb = tw[(pos + Q) << (14 - s)]; wmb.y = -wmb.y;
#pragma unroll
            for (int g = 0; g < 8; g += 4) {
#pragma unroll
                for (int j = 0; j < 2; j++) {
                    float2 wv = j ? wmb : wma;
                    float2 a = e[g + j], bq = e[g + j + 2];
                    e[g + j] = make_float2(a.x + bq.x, a.y + bq.y);
                    e[g + j + 2] = cmulf(make_float2(a.x - bq.x, a.y - bq.y), wv);
                }
            }
            float2 wl = tw[pos << (15 - s)]; wl.y = -wl.y;
#pragma unroll
            for (int j = 0; j < 8; j += 2) {
                float2 a = e[j], bq = e[j + 1];
                e[j] = make_float2(a.x + bq.x, a.y + bq.y);
                e[j + 1] = cmulf(make_float2(a.x - bq.x, a.y - bq.y), wl);
            }
#pragma unroll
            for (int j = 0; j < 8; j++) buf[base + j * Q] = e[j];
        }
        __syncthreads();
    }
    {
        float2 w0 = tw[0]; w0.y = -w0.y;
        for (int idx = tid; idx < 4096; idx += 512) {
            int base = idx * 2;
            float2 av = buf[base], bv = buf[base + 1];
            buf[base] = make_float2(av.x + bv.x, av.y + bv.y);
            float2 dv = make_float2(av.x - bv.x, av.y - bv.y);
            buf[base + 1] = cmulf(dv, w0);
        }
    }
    __syncthreads();
    for (int t = tid; t < Ff; t += 512) {
        float2 v = buf[__brev((unsigned)t) >> 19];
        float* cp = &g_conv[((size_t)bh * Ff + t) * 128];
        cp[c0] = v.x;
        cp[c1] = v.y;
    }
}

// ---------------- head coupling + gather + normalize + gate (256 threads) ----------
__global__ void __launch_bounds__(256) mix_kernel(const float* __restrict__ coupling) {
    __shared__ float convs[16 * 128];
    __shared__ float ys[16 * 128];
    __shared__ float coup[256];
    __shared__ float phiq[1024];
    __shared__ float den[16];
    int tid = threadIdx.x;
    int b = blockIdx.x >> 11, n = blockIdx.x & 2047;
    int fn = n < 2046 ? n : 2046;

    for (int i = tid; i < 2048; i += 256) {
        int g = i >> 7, c = i & 127;
        convs[i] = g_conv[(((size_t)(b * Hh + g)) * Ff + fn) * 128 + c];
    }
    if (tid < 256) coup[tid] = coupling[tid];
    for (int i = tid; i < 1024; i += 256) {
        int h = i >> 6, j = i & 63;
        phiq[i] = g_phiq[(((size_t)(b * Hh + h)) * Nn + n) * 64 + j];
    }
    __syncthreads();
    for (int i = tid; i < 2048; i += 256) {
        int h = i >> 7, c = i & 127;
        float acc = 0.f;
#pragma unroll
        for (int g = 0; g < 16; g++) acc += coup[h * 16 + g] * convs[g * 128 + c];
        ys[i] = acc;
    }
    __syncthreads();
    int warp = tid >> 5, lane = tid & 31;
    for (int h = warp; h < 16; h += 8) {
        float t1 = __fmul_rn(phiq[h * 64 + lane], ys[h * 128 + 64 + lane]);
        float t2 = __fmul_rn(phiq[h * 64 + 32 + lane], ys[h * 128 + 96 + lane]);
        float pv = __fadd_rn(t1, t2);
#pragma unroll
        for (int o = 16; o; o >>= 1)
            pv = __fadd_rn(pv, __shfl_down_sync(0xffffffffu, pv, o));
        pv = __shfl_sync(0xffffffffu, pv, 0);
        if (lane == 0) den[h] = __fadd_rn(fabsf(pv), 1e-4f);
    }
    __syncthreads();
    const float* grow = &g_qkvg[((size_t)b * Nn + n) * 4096 + 3072];
    float* arow = &g_att[((size_t)b * Nn + n) * 1024];
    for (int i = tid; i < 1024; i += 256) {
        int h = i >> 6;
        float sg = xla_sigmoid(grow[i]);
        arow[i] = phiq[i] * ys[h * 128 + (i & 63)] / den[h] * sg;
    }
}

// ---------------- launcher ----------------
extern "C" void kernel_launch(void* const* d_in, const int* in_sizes, int n_in,
                              void* d_out, int out_size) {
    const float* x       = (const float*)d_in[0];
    const float* w_qkvg  = (const float*)d_in[1];
    const float* b_qkvg  = (const float*)d_in[2];
    const float* w_out   = (const float*)d_in[3];
    const float* b_out   = (const float*)d_in[4];
    const float* qfm_w   = (const float*)d_in[5];
    const float* qfm_b   = (const float*)d_in[6];
    const float* kfm_w   = (const float*)d_in[7];
    const float* kfm_b   = (const float*)d_in[8];
    const float* wg_w    = (const float*)d_in[9];
    const float* wg_b    = (const float*)d_in[10];
    const float* ln_g    = (const float*)d_in[11];
    const float* ln_b    = (const float*)d_in[12];
    const float* sg_w1   = (const float*)d_in[13];
    const float* sg_b1   = (const float*)d_in[14];
    const float* sg_w2   = (const float*)d_in[15];
    const float* sg_b2   = (const float*)d_in[16];
    const float* wfreq   = (const float*)d_in[17];
    const float* wdamp   = (const float*)d_in[18];
    const float* wphase  = (const float*)d_in[19];
    const float* coupling= (const float*)d_in[20];
    (void)in_sizes; (void)n_in; (void)out_size;

    void* p;
    cudaGetSymbolAddress(&p, g_qkvg); float* qkvg = (float*)p;
    cudaGetSymbolAddress(&p, g_att);  float* att  = (float*)p;

    twid_kernel<<<16, 256>>>();
    cudaFuncSetAttribute(gemm_nt, cudaFuncAttributeMaxDynamicSharedMemorySize, GEMM_SMEM);
    gemm_nt<<<dim3(4096 / 128, 8192 / 128), 256, GEMM_SMEM>>>(x, w_qkvg, b_qkvg, qkvg, 8192, 4096, 1024);
    cudaFuncSetAttribute(kernfft_kernel, cudaFuncAttributeMaxDynamicSharedMemorySize, 131072);
    kernfft_kernel<<<Hh, 512, 131072>>>(wfreq, wdamp, wphase);
    featmap_kernel<<<Bb * Hh * FSPLIT, 256>>>(qfm_w, qfm_b, kfm_w, kfm_b, wg_w, wg_b);
    sg1_kernel<<<Bb * 4, 256>>>(ln_g, ln_b, sg_w1, sg_b1);
    sg2_kernel<<<Bb * 2, 256>>>(sg_w2, sg_b2);
    mod_kernel<<<dim3(Bb * Hh, (FBn + 255) / 256), 256>>>();
    cudaFuncSetAttribute(fft_conv_kernel, cudaFuncAttributeMaxDynamicSharedMemorySize, 98304);
    fft_conv_kernel<<<Bb * Hh * 64, 512, 98304>>>();
    mix_kernel<<<Bb * Nn, 256>>>(coupling);
    gemm_nt<<<dim3(1024 / 128, 8192 / 128), 256, GEMM_SMEM>>>(att, w_out, b_out, (float*)d_out, 8192, 1024, 1024);
}